// round 6
// baseline (speedup 1.0000x reference)
#include <cuda_runtime.h>
#include <cuda_bf16.h>
#include <math.h>
#include <stdint.h>

// ---------------- problem constants ----------------
#define HID     512      // H
#define HH      256      // Hh
#define G3      768      // 3*Hh
#define BATCH   16
#define NSENT   16
#define LW      128      // word seq len
#define NSEQW   256      // B*Nsent
#define MW      32768    // NSEQW*LW
#define WSLOT   (768 * 512)

// ---------------- device scratch (no mallocs allowed) ----------------
__device__ float g_xpw[2UL * MW * G3];        // word input gates, per dir
__device__ float g_outw[(size_t)MW * HID];    // word BiGRU outputs
__device__ float g_uw[(size_t)MW * HID];      // word attn pre-tanh proj
__device__ float g_sent[NSEQW * HID];         // sentence vectors
__device__ float g_xps[2 * BATCH * NSENT * G3];
__device__ float g_outs[BATCH * NSENT * HID];
__device__ float g_us[BATCH * NSENT * HID];
// bf16 split planes
__device__ __nv_bfloat16 g_Ahi[(size_t)MW * HID];
__device__ __nv_bfloat16 g_Alo[(size_t)MW * HID];
__device__ __nv_bfloat16 g_Whi[6 * WSLOT];
__device__ __nv_bfloat16 g_Wlo[6 * WSLOT];

// ---------------- helpers ----------------
__device__ __forceinline__ uint32_t smem_u32(const void* p) {
    uint32_t a;
    asm("{ .reg .u64 t; cvta.to.shared.u64 t, %1; cvt.u32.u64 %0, t; }" : "=r"(a) : "l"(p));
    return a;
}
__device__ __forceinline__ void ldsm4(uint32_t* r, uint32_t addr) {
    asm volatile("ldmatrix.sync.aligned.m8n8.x4.shared.b16 {%0,%1,%2,%3}, [%4];"
                 : "=r"(r[0]), "=r"(r[1]), "=r"(r[2]), "=r"(r[3]) : "r"(addr));
}
__device__ __forceinline__ void mma_bf16(float* c, const uint32_t* a, const uint32_t* b) {
    asm volatile("mma.sync.aligned.m16n8k16.row.col.f32.bf16.bf16.f32 "
                 "{%0,%1,%2,%3}, {%4,%5,%6,%7}, {%8,%9}, {%0,%1,%2,%3};"
                 : "+f"(c[0]), "+f"(c[1]), "+f"(c[2]), "+f"(c[3])
                 : "r"(a[0]), "r"(a[1]), "r"(a[2]), "r"(a[3]), "r"(b[0]), "r"(b[1]));
}

// ---------------- fp32 -> (bf16 hi, bf16 lo) split conversions ----------------
__device__ __forceinline__ void split4(float4 v, __nv_bfloat162* h, __nv_bfloat162* l) {
    float x[4] = {v.x, v.y, v.z, v.w};
    __nv_bfloat16 hh[4], ll[4];
#pragma unroll
    for (int i = 0; i < 4; i++) {
        hh[i] = __float2bfloat16_rn(x[i]);
        ll[i] = __float2bfloat16_rn(x[i] - __bfloat162float(hh[i]));
    }
    h[0] = __nv_bfloat162(hh[0], hh[1]); h[1] = __nv_bfloat162(hh[2], hh[3]);
    l[0] = __nv_bfloat162(ll[0], ll[1]); l[1] = __nv_bfloat162(ll[2], ll[3]);
}

__global__ void conv_split(const float4* __restrict__ src,
                           __nv_bfloat16* __restrict__ hi,
                           __nv_bfloat16* __restrict__ lo, int n4) {
    int i = blockIdx.x * blockDim.x + threadIdx.x;
    if (i >= n4) return;
    __nv_bfloat162 h[2], l[2];
    split4(src[i], h, l);
    ((__nv_bfloat162*)hi)[2 * i] = h[0]; ((__nv_bfloat162*)hi)[2 * i + 1] = h[1];
    ((__nv_bfloat162*)lo)[2 * i] = l[0]; ((__nv_bfloat162*)lo)[2 * i + 1] = l[1];
}

// gather variant: row m of A = token_feats[((m&2047)*16 + (m>>11))*512]
__global__ void conv_split_gather(const float4* __restrict__ tf,
                                  __nv_bfloat16* __restrict__ hi,
                                  __nv_bfloat16* __restrict__ lo) {
    int i = blockIdx.x * blockDim.x + threadIdx.x;
    if (i >= MW * 128) return;
    int m = i >> 7, kq = i & 127;
    float4 v = tf[((size_t)((m & 2047) * 16 + (m >> 11))) * 128 + kq];
    __nv_bfloat162 h[2], l[2];
    split4(v, h, l);
    ((__nv_bfloat162*)hi)[2 * i] = h[0]; ((__nv_bfloat162*)hi)[2 * i + 1] = h[1];
    ((__nv_bfloat162*)lo)[2 * i] = l[0]; ((__nv_bfloat162*)lo)[2 * i + 1] = l[1];
}

// ---------------- HMMA GEMM (unchanged, passing) ----------------
#define GEMM_SMEM 131072
__global__ void __launch_bounds__(256, 1)
gemm_tc(const __nv_bfloat16* __restrict__ Ahi, const __nv_bfloat16* __restrict__ Alo,
        const __nv_bfloat16* __restrict__ Bhi, const __nv_bfloat16* __restrict__ Blo,
        const float* __restrict__ bias, float* __restrict__ C, int ldc)
{
    extern __shared__ __align__(128) char smg[];
    const uint32_t sb = smem_u32(smg);
    const int tid = threadIdx.x;
    const int lane = tid & 31, wid = tid >> 5;
    const int wm = wid >> 2, wn = wid & 3;
    const int m0 = blockIdx.y * 128, n0 = blockIdx.x * 128;

    const __nv_bfloat16* planes[4] = {
        Ahi + (size_t)m0 * 512, Alo + (size_t)m0 * 512,
        Bhi + (size_t)n0 * 512, Blo + (size_t)n0 * 512 };

    const int rb = lane & 7;
    const int glA = lane >> 4;
    const int glB = lane >> 3;
    int aoff[4], boff[4];
#pragma unroll
    for (int mt = 0; mt < 4; mt++) {
        int r = wm * 64 + mt * 16 + rb + ((lane >> 3) & 1) * 8;
        aoff[mt] = ((r >> 3) << 10) + (rb << 7);
    }
#pragma unroll
    for (int nt = 0; nt < 4; nt++) {
        int r = wn * 32 + nt * 8 + rb;
        boff[nt] = ((r >> 3) << 10) + (rb << 7);
    }

    float acc[4][4][4];
#pragma unroll
    for (int a = 0; a < 4; a++)
#pragma unroll
        for (int b = 0; b < 4; b++)
#pragma unroll
            for (int d = 0; d < 4; d++) acc[a][b][d] = 0.f;

    const int ldg = tid & 7;
    const int ldr = tid >> 3;

#pragma unroll
    for (int i = 0; i < 16; i++) {
        const int pl = i >> 2;
        const int r = ((i & 3) << 5) + ldr;
        const __nv_bfloat16* src = planes[pl] + (size_t)r * 512 + ldg * 8;
        uint32_t dst = sb + pl * 16384 + ((r >> 3) << 10) + ((r & 7) << 7)
                       + ((ldg ^ (r & 7)) << 4);
        asm volatile("cp.async.cg.shared.global [%0], [%1], 16;" :: "r"(dst), "l"(src));
    }
    asm volatile("cp.async.commit_group;" ::: "memory");

    for (int c = 0; c < 8; c++) {
        asm volatile("cp.async.wait_group 0;" ::: "memory");
        __syncthreads();
        if (c < 7) {
            const int k0 = (c + 1) << 6;
            const uint32_t dbase = sb + ((c + 1) & 1) * 65536;
#pragma unroll
            for (int i = 0; i < 16; i++) {
                const int pl = i >> 2;
                const int r = ((i & 3) << 5) + ldr;
                const __nv_bfloat16* src = planes[pl] + (size_t)r * 512 + k0 + ldg * 8;
                uint32_t dst = dbase + pl * 16384 + ((r >> 3) << 10) + ((r & 7) << 7)
                               + ((ldg ^ (r & 7)) << 4);
                asm volatile("cp.async.cg.shared.global [%0], [%1], 16;" :: "r"(dst), "l"(src));
            }
            asm volatile("cp.async.commit_group;" ::: "memory");
        }

        const uint32_t bbase = sb + (c & 1) * 65536;
        uint32_t Bf[2][4][4];
#pragma unroll
        for (int s = 0; s < 4; s++) {
            if ((s & 1) == 0) {
                const int q0 = s << 1;
#pragma unroll
                for (int pl = 0; pl < 2; pl++)
#pragma unroll
                    for (int nt = 0; nt < 4; nt++)
                        ldsm4(Bf[pl][nt],
                              bbase + (2 + pl) * 16384 + boff[nt]
                              + (((q0 + glB) ^ rb) << 4));
            }
            uint32_t Af[2][4][4];
#pragma unroll
            for (int pl = 0; pl < 2; pl++)
#pragma unroll
                for (int mt = 0; mt < 4; mt++)
                    ldsm4(Af[pl][mt],
                          bbase + pl * 16384 + aoff[mt]
                          + ((((s << 1) + glA) ^ rb) << 4));
            const int ro = (s & 1) << 1;
#pragma unroll
            for (int mt = 0; mt < 4; mt++)
#pragma unroll
                for (int nt = 0; nt < 4; nt++) {
                    mma_bf16(acc[mt][nt], Af[0][mt], &Bf[0][nt][ro]);
                    mma_bf16(acc[mt][nt], Af[0][mt], &Bf[1][nt][ro]);
                    mma_bf16(acc[mt][nt], Af[1][mt], &Bf[0][nt][ro]);
                }
        }
    }

    const int rr = lane >> 2, cc = (lane & 3) * 2;
#pragma unroll
    for (int mt = 0; mt < 4; mt++) {
        const int row = m0 + wm * 64 + mt * 16 + rr;
#pragma unroll
        for (int nt = 0; nt < 4; nt++) {
            const int col = n0 + wn * 32 + nt * 8 + cc;
            const float b0 = bias[col], b1 = bias[col + 1];
            float2 v0 = {acc[mt][nt][0] + b0, acc[mt][nt][1] + b1};
            float2 v1 = {acc[mt][nt][2] + b0, acc[mt][nt][3] + b1};
            *(float2*)(C + (size_t)row * ldc + col) = v0;
            *(float2*)(C + (size_t)(row + 8) * ldc + col) = v1;
        }
    }
}

// ---------------- cluster-based persistent GRU ----------------
// grid (8 j-groups, nseq/SPB, 2 dirs), cluster (8,1,1) = one dependency group.
// W in smem as [gate][k4][jj] float4; h double-buffered seq-major in smem;
// h exchange via DSMEM pushes + HW cluster barrier (no global h traffic).
// FIX vs R5: no DSMEM push on the final step (its buffer is never read), and a
// trailing cluster barrier — so no remote store can target an exited CTA's smem.
template<int T, int SPB>
__global__ void __launch_bounds__(256, 1) __cluster_dims__(8, 1, 1)
gru_cluster(const float* __restrict__ xp_base,
            const float* __restrict__ whh_f, const float* __restrict__ whh_b,
            const float* __restrict__ bhh_f, const float* __restrict__ bhh_b,
            float* __restrict__ outbuf, int nseq)
{
    constexpr int SEQT = SPB / 8;           // seqs per thread
    extern __shared__ __align__(16) float smf[];
    float* Wv  = smf;                       // [3][64][32] float4
    float* hsm = smf + 3 * 64 * 32 * 4;     // [2][SPB][256]

    const int tid = threadIdx.x;
    const int jj = tid & 31, sl = tid >> 5;
    const int j0 = blockIdx.x * 32;
    const int sg0 = blockIdx.y * SPB;
    const int dir = blockIdx.z;
    const float* whh = dir ? whh_b : whh_f;
    const float* bhh = dir ? bhh_b : bhh_f;
    const float* xp  = xp_base + (size_t)dir * nseq * T * G3;
    const int j = j0 + jj;

    // stage W: Wv[g][k4][r] <- whh[(g*256 + j0 + r)*256 + 4*k4 ..]
    for (int i = tid; i < 3 * 64 * 32; i += 256) {
        int g = i >> 11, rem = i & 2047, k4 = rem >> 5, r = rem & 31;
        float4 v = *(const float4*)(whh + ((size_t)(g * 256 + j0 + r)) * 256 + k4 * 4);
        *(float4*)(Wv + 4 * i) = v;
    }
    // zero h buffer 0
    for (int i = tid; i < SPB * 256; i += 256) hsm[i] = 0.f;

    const uint32_t hsm_local = smem_u32(hsm);
    uint32_t peer[8];
#pragma unroll
    for (int r = 0; r < 8; r++)
        asm("mapa.shared::cluster.u32 %0, %1, %2;"
            : "=r"(peer[r]) : "r"(hsm_local), "r"(r));

    const float br = bhh[j], bz = bhh[256 + j], bn = bhh[512 + j];
    const uint32_t wbase = smem_u32(Wv) + jj * 16;
    __syncthreads();

    float xr_[SEQT], xz_[SEQT], xn_[SEQT];
    {
        const int tt = dir ? (T - 1) : 0;
#pragma unroll
        for (int q = 0; q < SEQT; q++) {
            const float* row = xp + ((size_t)(sg0 + sl * SEQT + q) * T + tt) * G3;
            xr_[q] = row[j]; xz_[q] = row[256 + j]; xn_[q] = row[512 + j];
        }
    }

    for (int step = 0; step < T; step++) {
        const int cur = step & 1, nxt = cur ^ 1;
        const int tt = dir ? (T - 1 - step) : step;
        const bool last = (step == T - 1);

        uint32_t hb[SEQT];
#pragma unroll
        for (int q = 0; q < SEQT; q++)
            hb[q] = hsm_local + (uint32_t)((cur * SPB + sl * SEQT + q) * 256) * 4;

        unsigned long long acc[3][SEQT];
#pragma unroll
        for (int g = 0; g < 3; g++)
#pragma unroll
            for (int q = 0; q < SEQT; q++) acc[g][q] = 0ULL;

#pragma unroll 8
        for (int k4 = 0; k4 < 64; k4++) {
            unsigned long long w0[3], w1[3];
#pragma unroll
            for (int g = 0; g < 3; g++)
                asm("ld.shared.v2.b64 {%0,%1}, [%2];"
                    : "=l"(w0[g]), "=l"(w1[g])
                    : "r"(wbase + g * 32768 + k4 * 512));
#pragma unroll
            for (int q = 0; q < SEQT; q++) {
                unsigned long long h0, h1;
                asm("ld.shared.v2.b64 {%0,%1}, [%2];"
                    : "=l"(h0), "=l"(h1) : "r"(hb[q] + k4 * 16));
#pragma unroll
                for (int g = 0; g < 3; g++) {
                    asm("fma.rn.f32x2 %0, %1, %2, %0;" : "+l"(acc[g][q]) : "l"(w0[g]), "l"(h0));
                    asm("fma.rn.f32x2 %0, %1, %2, %0;" : "+l"(acc[g][q]) : "l"(w1[g]), "l"(h1));
                }
            }
        }

        // gates, update, DSMEM push (not on last step), output store
#pragma unroll
        for (int q = 0; q < SEQT; q++) {
            const int s = sl * SEQT + q;
            float lo, hi, sR, sZ, sN;
            asm("mov.b64 {%0, %1}, %2;" : "=f"(lo), "=f"(hi) : "l"(acc[0][q])); sR = lo + hi;
            asm("mov.b64 {%0, %1}, %2;" : "=f"(lo), "=f"(hi) : "l"(acc[1][q])); sZ = lo + hi;
            asm("mov.b64 {%0, %1}, %2;" : "=f"(lo), "=f"(hi) : "l"(acc[2][q])); sN = lo + hi;
            const float hold = hsm[(cur * SPB + s) * 256 + j];
            const float r  = 1.f / (1.f + expf(-(xr_[q] + sR + br)));
            const float z  = 1.f / (1.f + expf(-(xz_[q] + sZ + bz)));
            const float nn = tanhf(xn_[q] + r * (sN + bn));
            const float hnew = (1.f - z) * nn + z * hold;
            if (!last) {
                const uint32_t off = (uint32_t)((nxt * SPB + s) * 256 + j) * 4;
                const uint32_t bits = __float_as_uint(hnew);
#pragma unroll
                for (int rk = 0; rk < 8; rk++)
                    asm volatile("st.shared::cluster.b32 [%0], %1;"
                                 :: "r"(peer[rk] + off), "r"(bits));
            }
            outbuf[((size_t)(sg0 + s) * T + tt) * HID + dir * HH + j] = hnew;
        }

        if (!last) {
            asm volatile("barrier.cluster.arrive.aligned;" ::: "memory");
            const int t2 = dir ? (T - 2 - step) : (step + 1);
#pragma unroll
            for (int q = 0; q < SEQT; q++) {
                const float* row = xp + ((size_t)(sg0 + sl * SEQT + q) * T + t2) * G3;
                xr_[q] = row[j]; xz_[q] = row[256 + j]; xn_[q] = row[512 + j];
            }
            asm volatile("barrier.cluster.wait.aligned;" ::: "memory");
        }
    }

    // no remote stores are in flight past the last barrier, but make exit
    // ordering explicit: no CTA leaves before all CTAs finish the loop.
    asm volatile("barrier.cluster.arrive.aligned;" ::: "memory");
    asm volatile("barrier.cluster.wait.aligned;" ::: "memory");
}

// ---------------- attention reduce (unchanged) ----------------
__global__ __launch_bounds__(256)
void attn_reduce(const float* __restrict__ u,
                 const float* __restrict__ feats,
                 const float* __restrict__ ctx,
                 float* __restrict__ dst,
                 int T)
{
    const int seq = blockIdx.x;
    const int tid = threadIdx.x;
    __shared__ float sctx[512];
    __shared__ float ssc[128];
    __shared__ float sred[256];

    for (int g = tid; g < 512; g += 256) sctx[g] = ctx[g];
    __syncthreads();

    const int lane = tid & 31, warp = tid >> 5;
    for (int t = warp; t < T; t += 8) {
        const float* ur = u + ((size_t)seq * T + t) * 512;
        float p = 0.f;
        for (int g = lane; g < 512; g += 32) p += tanhf(ur[g]) * sctx[g];
#pragma unroll
        for (int o = 16; o; o >>= 1) p += __shfl_down_sync(0xffffffffu, p, o);
        if (lane == 0) ssc[t] = p;
    }
    __syncthreads();

    float v = (tid < T) ? ssc[tid] : -1e30f;
    sred[tid] = v; __syncthreads();
    for (int o = 128; o; o >>= 1) { if (tid < o) sred[tid] = fmaxf(sred[tid], sred[tid + o]); __syncthreads(); }
    float mx = sred[0]; __syncthreads();
    float e = (tid < T) ? expf(v - mx) : 0.f;
    sred[tid] = e; __syncthreads();
    for (int o = 128; o; o >>= 1) { if (tid < o) sred[tid] += sred[tid + o]; __syncthreads(); }
    float inv = 1.f / sred[0]; __syncthreads();
    if (tid < T) ssc[tid] = e * inv;
    __syncthreads();

    for (int h = tid; h < 512; h += 256) {
        float acc = 0.f;
        for (int t = 0; t < T; t++)
            acc = fmaf(ssc[t], feats[((size_t)seq * T + t) * 512 + h], acc);
        dst[(size_t)seq * 512 + h] = acc;
    }
}

// ---------------- host ----------------
extern "C" void kernel_launch(void* const* d_in, const int* in_sizes, int n_in,
                              void* d_out, int out_size)
{
    const float* tf       = (const float*)d_in[0];
    const float* w_wih_f  = (const float*)d_in[2];
    const float* w_whh_f  = (const float*)d_in[3];
    const float* w_bih_f  = (const float*)d_in[4];
    const float* w_bhh_f  = (const float*)d_in[5];
    const float* w_wih_b  = (const float*)d_in[6];
    const float* w_whh_b  = (const float*)d_in[7];
    const float* w_bih_b  = (const float*)d_in[8];
    const float* w_bhh_b  = (const float*)d_in[9];
    const float* s_wih_f  = (const float*)d_in[10];
    const float* s_whh_f  = (const float*)d_in[11];
    const float* s_bih_f  = (const float*)d_in[12];
    const float* s_bhh_f  = (const float*)d_in[13];
    const float* s_wih_b  = (const float*)d_in[14];
    const float* s_whh_b  = (const float*)d_in[15];
    const float* s_bih_b  = (const float*)d_in[16];
    const float* s_bhh_b  = (const float*)d_in[17];
    const float* w_attn_w = (const float*)d_in[18];
    const float* w_attn_b = (const float*)d_in[19];
    const float* w_ctx    = (const float*)d_in[20];
    const float* s_attn_w = (const float*)d_in[21];
    const float* s_attn_b = (const float*)d_in[22];
    const float* s_ctx    = (const float*)d_in[23];

    float *xpw, *outw, *uw, *sent, *xps, *outs, *us;
    __nv_bfloat16 *Ahi, *Alo, *Whi, *Wlo;
    cudaGetSymbolAddress((void**)&xpw,  g_xpw);
    cudaGetSymbolAddress((void**)&outw, g_outw);
    cudaGetSymbolAddress((void**)&uw,   g_uw);
    cudaGetSymbolAddress((void**)&sent, g_sent);
    cudaGetSymbolAddress((void**)&xps,  g_xps);
    cudaGetSymbolAddress((void**)&outs, g_outs);
    cudaGetSymbolAddress((void**)&us,   g_us);
    cudaGetSymbolAddress((void**)&Ahi,  g_Ahi);
    cudaGetSymbolAddress((void**)&Alo,  g_Alo);
    cudaGetSymbolAddress((void**)&Whi,  g_Whi);
    cudaGetSymbolAddress((void**)&Wlo,  g_Wlo);

    const size_t smw = (3 * 64 * 32 * 4 + 2 * 32 * 256) * sizeof(float);  // 163,840
    const size_t sms = (3 * 64 * 32 * 4 + 2 * 16 * 256) * sizeof(float);  // 131,072
    cudaFuncSetAttribute(gru_cluster<LW, 32>,
                         cudaFuncAttributeMaxDynamicSharedMemorySize, (int)smw);
    cudaFuncSetAttribute(gru_cluster<NSENT, 16>,
                         cudaFuncAttributeMaxDynamicSharedMemorySize, (int)sms);
    cudaFuncSetAttribute(gemm_tc,
                         cudaFuncAttributeMaxDynamicSharedMemorySize, GEMM_SMEM);

    // 0) weight splits (6 slots)
    const float* wsrc[6] = {w_wih_f, w_wih_b, w_attn_w, s_wih_f, s_wih_b, s_attn_w};
    const int    wrows[6] = {768, 768, 512, 768, 768, 512};
    for (int i = 0; i < 6; i++) {
        int n4 = wrows[i] * 128;
        conv_split<<<(n4 + 255) / 256, 256>>>((const float4*)wsrc[i],
                                              Whi + (size_t)i * WSLOT,
                                              Wlo + (size_t)i * WSLOT, n4);
    }

    // 1) gather + split token_feats; word input-gate GEMMs (tensor cores)
    conv_split_gather<<<(MW * 128 + 255) / 256, 256>>>((const float4*)tf, Ahi, Alo);
    {
        dim3 g(6, 256);
        gemm_tc<<<g, 256, GEMM_SMEM>>>(Ahi, Alo, Whi, Wlo, w_bih_f, xpw, G3);
        gemm_tc<<<g, 256, GEMM_SMEM>>>(Ahi, Alo, Whi + WSLOT, Wlo + WSLOT, w_bih_b,
                                       xpw + (size_t)MW * G3, G3);
    }

    // 2) word BiGRU recurrence: 16 independent 8-CTA clusters, DSMEM exchange
    {
        dim3 g(8, NSEQW / 32, 2);
        gru_cluster<LW, 32><<<g, 256, smw>>>(xpw, w_whh_f, w_whh_b, w_bhh_f, w_bhh_b,
                                             outw, NSEQW);
    }

    // 3) word attention projection (tc) + fused reduce
    conv_split<<<(MW * 128 + 255) / 256, 256>>>((const float4*)outw, Ahi, Alo, MW * 128);
    {
        dim3 g(4, 256);
        gemm_tc<<<g, 256, GEMM_SMEM>>>(Ahi, Alo, Whi + 2 * WSLOT, Wlo + 2 * WSLOT,
                                       w_attn_b, uw, HID);
        attn_reduce<<<NSEQW, 256>>>(uw, outw, w_ctx, sent, LW);
    }

    // 4) sentence input-gate GEMMs (tc)
    conv_split<<<(NSEQW * 128 + 255) / 256, 256>>>((const float4*)sent, Ahi, Alo, NSEQW * 128);
    {
        dim3 g(6, 2);
        gemm_tc<<<g, 256, GEMM_SMEM>>>(Ahi, Alo, Whi + 3 * WSLOT, Wlo + 3 * WSLOT,
                                       s_bih_f, xps, G3);
        gemm_tc<<<g, 256, GEMM_SMEM>>>(Ahi, Alo, Whi + 4 * WSLOT, Wlo + 4 * WSLOT,
                                       s_bih_b, xps + (size_t)BATCH * NSENT * G3, G3);
    }

    // 5) sentence BiGRU: 2 clusters of 8 CTAs
    {
        dim3 g(8, 1, 2);
        gru_cluster<NSENT, 16><<<g, 256, sms>>>(xps, s_whh_f, s_whh_b, s_bhh_f, s_bhh_b,
                                                outs, BATCH);
    }

    // 6) sentence attention (tc) -> output
    conv_split<<<(NSEQW * 128 + 255) / 256, 256>>>((const float4*)outs, Ahi, Alo, NSEQW * 128);
    {
        dim3 g(4, 2);
        gemm_tc<<<g, 256, GEMM_SMEM>>>(Ahi, Alo, Whi + 5 * WSLOT, Wlo + 5 * WSLOT,
                                       s_attn_b, us, HID);
        attn_reduce<<<BATCH, 256>>>(us, outs, s_ctx, (float*)d_out, NSENT);
    }
}

// round 7
// speedup vs baseline: 1.2334x; 1.2334x over previous
#include <cuda_runtime.h>
#include <cuda_bf16.h>
#include <math.h>
#include <stdint.h>

// ---------------- problem constants ----------------
#define HID     512      // H
#define HH      256      // Hh
#define G3      768      // 3*Hh
#define BATCH   16
#define NSENT   16
#define LW      128      // word seq len
#define NSEQW   256      // B*Nsent
#define MW      32768    // NSEQW*LW
#define WSLOT   (768 * 512)

// ---------------- device scratch (no mallocs allowed) ----------------
__device__ float g_xpw[2UL * MW * G3];        // word input gates, per dir
__device__ float g_outw[(size_t)MW * HID];    // word BiGRU outputs
__device__ float g_uw[(size_t)MW * HID];      // word attn pre-tanh proj
__device__ float g_sent[NSEQW * HID];         // sentence vectors
__device__ float g_xps[2 * BATCH * NSENT * G3];
__device__ float g_outs[BATCH * NSENT * HID];
__device__ float g_us[BATCH * NSENT * HID];
// h ping-pong, layout [phase][dir][seq][j(256)]
__device__ float g_hw[2 * 2 * HH * NSEQW];
__device__ float g_hs[2 * 2 * HH * BATCH];
__device__ unsigned g_barw_cnt[16], g_barw_sense[16];   // 16 groups of 8 blocks
__device__ unsigned g_bars_cnt[2],  g_bars_sense[2];
// bf16 split planes
__device__ __nv_bfloat16 g_Ahi[(size_t)MW * HID];
__device__ __nv_bfloat16 g_Alo[(size_t)MW * HID];
__device__ __nv_bfloat16 g_Whi[6 * WSLOT];
__device__ __nv_bfloat16 g_Wlo[6 * WSLOT];

// ---------------- helpers ----------------
__device__ __forceinline__ uint32_t smem_u32(const void* p) {
    uint32_t a;
    asm("{ .reg .u64 t; cvta.to.shared.u64 t, %1; cvt.u32.u64 %0, t; }" : "=r"(a) : "l"(p));
    return a;
}
__device__ __forceinline__ void ldsm4(uint32_t* r, uint32_t addr) {
    asm volatile("ldmatrix.sync.aligned.m8n8.x4.shared.b16 {%0,%1,%2,%3}, [%4];"
                 : "=r"(r[0]), "=r"(r[1]), "=r"(r[2]), "=r"(r[3]) : "r"(addr));
}
__device__ __forceinline__ void mma_bf16(float* c, const uint32_t* a, const uint32_t* b) {
    asm volatile("mma.sync.aligned.m16n8k16.row.col.f32.bf16.bf16.f32 "
                 "{%0,%1,%2,%3}, {%4,%5,%6,%7}, {%8,%9}, {%0,%1,%2,%3};"
                 : "+f"(c[0]), "+f"(c[1]), "+f"(c[2]), "+f"(c[3])
                 : "r"(a[0]), "r"(a[1]), "r"(a[2]), "r"(a[3]), "r"(b[0]), "r"(b[1]));
}

// ---------------- fp32 -> (bf16 hi, bf16 lo) split conversions ----------------
__device__ __forceinline__ void split4(float4 v, __nv_bfloat162* h, __nv_bfloat162* l) {
    float x[4] = {v.x, v.y, v.z, v.w};
    __nv_bfloat16 hh[4], ll[4];
#pragma unroll
    for (int i = 0; i < 4; i++) {
        hh[i] = __float2bfloat16_rn(x[i]);
        ll[i] = __float2bfloat16_rn(x[i] - __bfloat162float(hh[i]));
    }
    h[0] = __nv_bfloat162(hh[0], hh[1]); h[1] = __nv_bfloat162(hh[2], hh[3]);
    l[0] = __nv_bfloat162(ll[0], ll[1]); l[1] = __nv_bfloat162(ll[2], ll[3]);
}

__global__ void conv_split(const float4* __restrict__ src,
                           __nv_bfloat16* __restrict__ hi,
                           __nv_bfloat16* __restrict__ lo, int n4) {
    int i = blockIdx.x * blockDim.x + threadIdx.x;
    if (i >= n4) return;
    __nv_bfloat162 h[2], l[2];
    split4(src[i], h, l);
    ((__nv_bfloat162*)hi)[2 * i] = h[0]; ((__nv_bfloat162*)hi)[2 * i + 1] = h[1];
    ((__nv_bfloat162*)lo)[2 * i] = l[0]; ((__nv_bfloat162*)lo)[2 * i + 1] = l[1];
}

// gather variant: row m of A = token_feats[((m&2047)*16 + (m>>11))*512]
__global__ void conv_split_gather(const float4* __restrict__ tf,
                                  __nv_bfloat16* __restrict__ hi,
                                  __nv_bfloat16* __restrict__ lo) {
    int i = blockIdx.x * blockDim.x + threadIdx.x;
    if (i >= MW * 128) return;
    int m = i >> 7, kq = i & 127;
    float4 v = tf[((size_t)((m & 2047) * 16 + (m >> 11))) * 128 + kq];
    __nv_bfloat162 h[2], l[2];
    split4(v, h, l);
    ((__nv_bfloat162*)hi)[2 * i] = h[0]; ((__nv_bfloat162*)hi)[2 * i + 1] = h[1];
    ((__nv_bfloat162*)lo)[2 * i] = l[0]; ((__nv_bfloat162*)lo)[2 * i + 1] = l[1];
}

// ---------------- HMMA GEMM (unchanged, passing) ----------------
#define GEMM_SMEM 131072
__global__ void __launch_bounds__(256, 1)
gemm_tc(const __nv_bfloat16* __restrict__ Ahi, const __nv_bfloat16* __restrict__ Alo,
        const __nv_bfloat16* __restrict__ Bhi, const __nv_bfloat16* __restrict__ Blo,
        const float* __restrict__ bias, float* __restrict__ C, int ldc)
{
    extern __shared__ __align__(128) char smg[];
    const uint32_t sb = smem_u32(smg);
    const int tid = threadIdx.x;
    const int lane = tid & 31, wid = tid >> 5;
    const int wm = wid >> 2, wn = wid & 3;
    const int m0 = blockIdx.y * 128, n0 = blockIdx.x * 128;

    const __nv_bfloat16* planes[4] = {
        Ahi + (size_t)m0 * 512, Alo + (size_t)m0 * 512,
        Bhi + (size_t)n0 * 512, Blo + (size_t)n0 * 512 };

    const int rb = lane & 7;
    const int glA = lane >> 4;
    const int glB = lane >> 3;
    int aoff[4], boff[4];
#pragma unroll
    for (int mt = 0; mt < 4; mt++) {
        int r = wm * 64 + mt * 16 + rb + ((lane >> 3) & 1) * 8;
        aoff[mt] = ((r >> 3) << 10) + (rb << 7);
    }
#pragma unroll
    for (int nt = 0; nt < 4; nt++) {
        int r = wn * 32 + nt * 8 + rb;
        boff[nt] = ((r >> 3) << 10) + (rb << 7);
    }

    float acc[4][4][4];
#pragma unroll
    for (int a = 0; a < 4; a++)
#pragma unroll
        for (int b = 0; b < 4; b++)
#pragma unroll
            for (int d = 0; d < 4; d++) acc[a][b][d] = 0.f;

    const int ldg = tid & 7;
    const int ldr = tid >> 3;

#pragma unroll
    for (int i = 0; i < 16; i++) {
        const int pl = i >> 2;
        const int r = ((i & 3) << 5) + ldr;
        const __nv_bfloat16* src = planes[pl] + (size_t)r * 512 + ldg * 8;
        uint32_t dst = sb + pl * 16384 + ((r >> 3) << 10) + ((r & 7) << 7)
                       + ((ldg ^ (r & 7)) << 4);
        asm volatile("cp.async.cg.shared.global [%0], [%1], 16;" :: "r"(dst), "l"(src));
    }
    asm volatile("cp.async.commit_group;" ::: "memory");

    for (int c = 0; c < 8; c++) {
        asm volatile("cp.async.wait_group 0;" ::: "memory");
        __syncthreads();
        if (c < 7) {
            const int k0 = (c + 1) << 6;
            const uint32_t dbase = sb + ((c + 1) & 1) * 65536;
#pragma unroll
            for (int i = 0; i < 16; i++) {
                const int pl = i >> 2;
                const int r = ((i & 3) << 5) + ldr;
                const __nv_bfloat16* src = planes[pl] + (size_t)r * 512 + k0 + ldg * 8;
                uint32_t dst = dbase + pl * 16384 + ((r >> 3) << 10) + ((r & 7) << 7)
                               + ((ldg ^ (r & 7)) << 4);
                asm volatile("cp.async.cg.shared.global [%0], [%1], 16;" :: "r"(dst), "l"(src));
            }
            asm volatile("cp.async.commit_group;" ::: "memory");
        }

        const uint32_t bbase = sb + (c & 1) * 65536;
        uint32_t Bf[2][4][4];
#pragma unroll
        for (int s = 0; s < 4; s++) {
            if ((s & 1) == 0) {
                const int q0 = s << 1;
#pragma unroll
                for (int pl = 0; pl < 2; pl++)
#pragma unroll
                    for (int nt = 0; nt < 4; nt++)
                        ldsm4(Bf[pl][nt],
                              bbase + (2 + pl) * 16384 + boff[nt]
                              + (((q0 + glB) ^ rb) << 4));
            }
            uint32_t Af[2][4][4];
#pragma unroll
            for (int pl = 0; pl < 2; pl++)
#pragma unroll
                for (int mt = 0; mt < 4; mt++)
                    ldsm4(Af[pl][mt],
                          bbase + pl * 16384 + aoff[mt]
                          + ((((s << 1) + glA) ^ rb) << 4));
            const int ro = (s & 1) << 1;
#pragma unroll
            for (int mt = 0; mt < 4; mt++)
#pragma unroll
                for (int nt = 0; nt < 4; nt++) {
                    mma_bf16(acc[mt][nt], Af[0][mt], &Bf[0][nt][ro]);
                    mma_bf16(acc[mt][nt], Af[0][mt], &Bf[1][nt][ro]);
                    mma_bf16(acc[mt][nt], Af[1][mt], &Bf[0][nt][ro]);
                }
        }
    }

    const int rr = lane >> 2, cc = (lane & 3) * 2;
#pragma unroll
    for (int mt = 0; mt < 4; mt++) {
        const int row = m0 + wm * 64 + mt * 16 + rr;
#pragma unroll
        for (int nt = 0; nt < 4; nt++) {
            const int col = n0 + wn * 32 + nt * 8 + cc;
            const float b0 = bias[col], b1 = bias[col + 1];
            float2 v0 = {acc[mt][nt][0] + b0, acc[mt][nt][1] + b1};
            float2 v1 = {acc[mt][nt][2] + b0, acc[mt][nt][3] + b1};
            *(float2*)(C + (size_t)row * ldc + col) = v0;
            *(float2*)(C + (size_t)(row + 8) * ldc + col) = v1;
        }
    }
}

// ---------------- group barrier (R4-proven) ----------------
__device__ __forceinline__ unsigned ld_acq(const unsigned* p) {
    unsigned v;
    asm volatile("ld.acquire.gpu.u32 %0, [%1];" : "=r"(v) : "l"(p) : "memory");
    return v;
}
__device__ __forceinline__ void group_barrier(unsigned* cnt, unsigned* sense,
                                              unsigned target, int total) {
    __syncthreads();
    if (threadIdx.x == 0) {
        __threadfence();
        unsigned t = atomicAdd(cnt, 1u);
        if (t == (unsigned)(total - 1)) {
            *cnt = 0u;
            asm volatile("red.release.gpu.add.u32 [%0], 1;" :: "l"(sense) : "memory");
        } else {
            while (ld_acq(sense) != target) { }
        }
    }
    __syncthreads();
}

// ---------------- persistent GRU, W_hh in REGISTERS ----------------
// grid (8 j-groups, nseq/SPB, 2 dirs); 256 thr = 32 jj x 8 k-slices.
// Thread (jj, ks) holds W rows (3 gates, j=j0+jj) for k in {m*32+ks*4+c},
// packed as f32x2 pairs (96 floats in regs, loaded once). Per seq: 8
// conflict-free LDS.128 broadcasts of h chunks, 48 FFMA2, shfl.xor reduce
// over the 8 k-slice lanes. h exchanged via global [seq][j] + group barrier.
template<int T, int SPB>
__global__ void __launch_bounds__(256, 1)
gru_reg(const float* __restrict__ xp_base,
        const float* __restrict__ whh_f, const float* __restrict__ whh_b,
        const float* __restrict__ bhh_f, const float* __restrict__ bhh_b,
        float* __restrict__ hbuf,            // [2][2][nseq][256]
        float* __restrict__ outbuf,
        unsigned* cnt_arr, unsigned* sense_arr, int nseq)
{
    constexpr int SEQL = SPB / 8;            // seqs per lane (s % 8 == ks)
    constexpr int HROW = 264;                // floats per hsm row (16B-aligned)
    __shared__ __align__(16) float hsm[SPB * HROW];
    __shared__ float xs[32 * (SPB + 1)];

    const int tid = threadIdx.x;
    const int jj = tid >> 3;                 // 0..31
    const int ks = tid & 7;                  // k-slice lane
    const int j0 = blockIdx.x * 32;
    const int sg0 = blockIdx.y * SPB;
    const int dir = blockIdx.z;
    const int gidx = blockIdx.z * gridDim.y + blockIdx.y;
    unsigned* bcnt = cnt_arr + gidx;
    unsigned* bsense = sense_arr + gidx;
    const float* whh = dir ? whh_b : whh_f;
    const float* bhh = dir ? bhh_b : bhh_f;
    const float* xp  = xp_base + (size_t)dir * nseq * T * G3;
    const int j = j0 + jj;

    // ---- W_hh into registers (once) ----
    unsigned long long Wp[3][8][2];
#pragma unroll
    for (int g = 0; g < 3; g++)
#pragma unroll
        for (int m = 0; m < 8; m++) {
            float4 v = *(const float4*)(whh + ((size_t)(g * 256 + j)) * 256
                                        + m * 32 + ks * 4);
            asm("mov.b64 %0, {%1,%2};" : "=l"(Wp[g][m][0]) : "f"(v.x), "f"(v.y));
            asm("mov.b64 %0, {%1,%2};" : "=l"(Wp[g][m][1]) : "f"(v.z), "f"(v.w));
        }

    const float br = bhh[j], bz = bhh[256 + j], bn = bhh[512 + j];
    const uint32_t hbase = smem_u32(hsm);
    const unsigned base = ld_acq(bsense);

    // prefetch step-0 input-gate terms (lane's seqs: s = q*8 + ks)
    float xr_[SEQL], xz_[SEQL], xn_[SEQL];
    {
        const int tt = dir ? (T - 1) : 0;
#pragma unroll
        for (int q = 0; q < SEQL; q++) {
            const float* row = xp + ((size_t)(sg0 + q * 8 + ks) * T + tt) * G3;
            xr_[q] = row[j]; xz_[q] = row[256 + j]; xn_[q] = row[512 + j];
        }
    }

    for (int step = 0; step < T; step++) {
        const int tt = dir ? (T - 1 - step) : step;

        // ---- stage h(t) into hsm[s][k] ----
        if (step == 0) {
            for (int e = tid; e < SPB * HROW; e += 256) hsm[e] = 0.f;
        } else {
            const float* hcur = hbuf + ((size_t)((step & 1) * 2 + dir)) * nseq * 256
                                + (size_t)sg0 * 256;
#pragma unroll 4
            for (int e = tid; e < SPB * 256; e += 256) {
                int s = e >> 8, k = e & 255;
                hsm[s * HROW + k] = hcur[s * 256 + k];   // LDG + STS conflict-free
            }
        }
        __syncthreads();

        // ---- compute: per seq, partial dots + lane reduce ----
        float svR[SEQL], svZ[SEQL], svN[SEQL];
#pragma unroll
        for (int q = 0; q < SEQL; q++) {
            uint32_t ha = hbase + (uint32_t)(q * 8) * (HROW * 4) + ks * 16;
            for (int s8 = 0; s8 < 8; s8++, ha += HROW * 4) {
                unsigned long long a0 = 0ULL, a1 = 0ULL, a2 = 0ULL;
#pragma unroll
                for (int m = 0; m < 8; m++) {
                    unsigned long long h0, h1;
                    asm("ld.shared.v2.b64 {%0,%1}, [%2];"
                        : "=l"(h0), "=l"(h1) : "r"(ha + m * 128));
                    asm("fma.rn.f32x2 %0, %1, %2, %0;" : "+l"(a0) : "l"(Wp[0][m][0]), "l"(h0));
                    asm("fma.rn.f32x2 %0, %1, %2, %0;" : "+l"(a1) : "l"(Wp[1][m][0]), "l"(h0));
                    asm("fma.rn.f32x2 %0, %1, %2, %0;" : "+l"(a2) : "l"(Wp[2][m][0]), "l"(h0));
                    asm("fma.rn.f32x2 %0, %1, %2, %0;" : "+l"(a0) : "l"(Wp[0][m][1]), "l"(h1));
                    asm("fma.rn.f32x2 %0, %1, %2, %0;" : "+l"(a1) : "l"(Wp[1][m][1]), "l"(h1));
                    asm("fma.rn.f32x2 %0, %1, %2, %0;" : "+l"(a2) : "l"(Wp[2][m][1]), "l"(h1));
                }
                float lo, hi;
                asm("mov.b64 {%0,%1}, %2;" : "=f"(lo), "=f"(hi) : "l"(a0));
                float r_ = lo + hi;
                asm("mov.b64 {%0,%1}, %2;" : "=f"(lo), "=f"(hi) : "l"(a1));
                float z_ = lo + hi;
                asm("mov.b64 {%0,%1}, %2;" : "=f"(lo), "=f"(hi) : "l"(a2));
                float n_ = lo + hi;
#pragma unroll
                for (int o = 1; o <= 4; o <<= 1) {
                    r_ += __shfl_xor_sync(0xffffffffu, r_, o);
                    z_ += __shfl_xor_sync(0xffffffffu, z_, o);
                    n_ += __shfl_xor_sync(0xffffffffu, n_, o);
                }
                if (ks == s8) { svR[q] = r_; svZ[q] = z_; svN[q] = n_; }
            }
        }

        // ---- gates + h update (lane handles its 4 seqs) ----
#pragma unroll
        for (int q = 0; q < SEQL; q++) {
            const int s = q * 8 + ks;
            const float hold = hsm[s * HROW + j];
            const float r  = 1.f / (1.f + expf(-(xr_[q] + svR[q] + br)));
            const float z  = 1.f / (1.f + expf(-(xz_[q] + svZ[q] + bz)));
            const float nn = tanhf(xn_[q] + r * (svN[q] + bn));
            const float hnew = (1.f - z) * nn + z * hold;
            xs[jj * (SPB + 1) + s] = hnew;
            outbuf[((size_t)(sg0 + s) * T + tt) * HID + dir * HH + j] = hnew;
        }
        __syncthreads();

        if (step < T - 1) {
            // coalesced h(t+1) write-out: [seq][j] global layout
            float* hnext = hbuf + ((size_t)(((step + 1) & 1) * 2 + dir)) * nseq * 256
                           + (size_t)sg0 * 256;
#pragma unroll
            for (int e = tid; e < SPB * 32; e += 256) {
                int s = e >> 5, jr = e & 31;
                hnext[s * 256 + j0 + jr] = xs[jr * (SPB + 1) + s];
            }
            // prefetch next step's xp before spinning on the barrier
            const int t2 = dir ? (T - 2 - step) : (step + 1);
#pragma unroll
            for (int q = 0; q < SEQL; q++) {
                const float* row = xp + ((size_t)(sg0 + q * 8 + ks) * T + t2) * G3;
                xr_[q] = row[j]; xz_[q] = row[256 + j]; xn_[q] = row[512 + j];
            }
            group_barrier(bcnt, bsense, base + (unsigned)step + 1u, 8);
        }
    }
}

// ---------------- attention reduce (unchanged) ----------------
__global__ __launch_bounds__(256)
void attn_reduce(const float* __restrict__ u,
                 const float* __restrict__ feats,
                 const float* __restrict__ ctx,
                 float* __restrict__ dst,
                 int T)
{
    const int seq = blockIdx.x;
    const int tid = threadIdx.x;
    __shared__ float sctx[512];
    __shared__ float ssc[128];
    __shared__ float sred[256];

    for (int g = tid; g < 512; g += 256) sctx[g] = ctx[g];
    __syncthreads();

    const int lane = tid & 31, warp = tid >> 5;
    for (int t = warp; t < T; t += 8) {
        const float* ur = u + ((size_t)seq * T + t) * 512;
        float p = 0.f;
        for (int g = lane; g < 512; g += 32) p += tanhf(ur[g]) * sctx[g];
#pragma unroll
        for (int o = 16; o; o >>= 1) p += __shfl_down_sync(0xffffffffu, p, o);
        if (lane == 0) ssc[t] = p;
    }
    __syncthreads();

    float v = (tid < T) ? ssc[tid] : -1e30f;
    sred[tid] = v; __syncthreads();
    for (int o = 128; o; o >>= 1) { if (tid < o) sred[tid] = fmaxf(sred[tid], sred[tid + o]); __syncthreads(); }
    float mx = sred[0]; __syncthreads();
    float e = (tid < T) ? expf(v - mx) : 0.f;
    sred[tid] = e; __syncthreads();
    for (int o = 128; o; o >>= 1) { if (tid < o) sred[tid] += sred[tid + o]; __syncthreads(); }
    float inv = 1.f / sred[0]; __syncthreads();
    if (tid < T) ssc[tid] = e * inv;
    __syncthreads();

    for (int h = tid; h < 512; h += 256) {
        float acc = 0.f;
        for (int t = 0; t < T; t++)
            acc = fmaf(ssc[t], feats[((size_t)seq * T + t) * 512 + h], acc);
        dst[(size_t)seq * 512 + h] = acc;
    }
}

// ---------------- host ----------------
extern "C" void kernel_launch(void* const* d_in, const int* in_sizes, int n_in,
                              void* d_out, int out_size)
{
    const float* tf       = (const float*)d_in[0];
    const float* w_wih_f  = (const float*)d_in[2];
    const float* w_whh_f  = (const float*)d_in[3];
    const float* w_bih_f  = (const float*)d_in[4];
    const float* w_bhh_f  = (const float*)d_in[5];
    const float* w_wih_b  = (const float*)d_in[6];
    const float* w_whh_b  = (const float*)d_in[7];
    const float* w_bih_b  = (const float*)d_in[8];
    const float* w_bhh_b  = (const float*)d_in[9];
    const float* s_wih_f  = (const float*)d_in[10];
    const float* s_whh_f  = (const float*)d_in[11];
    const float* s_bih_f  = (const float*)d_in[12];
    const float* s_bhh_f  = (const float*)d_in[13];
    const float* s_wih_b  = (const float*)d_in[14];
    const float* s_whh_b  = (const float*)d_in[15];
    const float* s_bih_b  = (const float*)d_in[16];
    const float* s_bhh_b  = (const float*)d_in[17];
    const float* w_attn_w = (const float*)d_in[18];
    const float* w_attn_b = (const float*)d_in[19];
    const float* w_ctx    = (const float*)d_in[20];
    const float* s_attn_w = (const float*)d_in[21];
    const float* s_attn_b = (const float*)d_in[22];
    const float* s_ctx    = (const float*)d_in[23];

    float *xpw, *outw, *uw, *sent, *xps, *outs, *us, *hw, *hs;
    unsigned *bwc, *bws, *bsc, *bss;
    __nv_bfloat16 *Ahi, *Alo, *Whi, *Wlo;
    cudaGetSymbolAddress((void**)&xpw,  g_xpw);
    cudaGetSymbolAddress((void**)&outw, g_outw);
    cudaGetSymbolAddress((void**)&uw,   g_uw);
    cudaGetSymbolAddress((void**)&sent, g_sent);
    cudaGetSymbolAddress((void**)&xps,  g_xps);
    cudaGetSymbolAddress((void**)&outs, g_outs);
    cudaGetSymbolAddress((void**)&us,   g_us);
    cudaGetSymbolAddress((void**)&hw,   g_hw);
    cudaGetSymbolAddress((void**)&hs,   g_hs);
    cudaGetSymbolAddress((void**)&bwc,  g_barw_cnt);
    cudaGetSymbolAddress((void**)&bws,  g_barw_sense);
    cudaGetSymbolAddress((void**)&bsc,  g_bars_cnt);
    cudaGetSymbolAddress((void**)&bss,  g_bars_sense);
    cudaGetSymbolAddress((void**)&Ahi,  g_Ahi);
    cudaGetSymbolAddress((void**)&Alo,  g_Alo);
    cudaGetSymbolAddress((void**)&Whi,  g_Whi);
    cudaGetSymbolAddress((void**)&Wlo,  g_Wlo);

    cudaFuncSetAttribute(gemm_tc,
                         cudaFuncAttributeMaxDynamicSharedMemorySize, GEMM_SMEM);

    const float* wsrc[6] = {w_wih_f, w_wih_b, w_attn_w, s_wih_f, s_wih_b, s_attn_w};
    const int    wrows[6] = {768, 768, 512, 768, 768, 512};
    auto wsplit = [&](int i) {
        int n4 = wrows[i] * 128;
        conv_split<<<(n4 + 255) / 256, 256>>>((const float4*)wsrc[i],
                                              Whi + (size_t)i * WSLOT,
                                              Wlo + (size_t)i * WSLOT, n4);
    };

    // launches 1-2: word weight splits
    wsplit(0); wsplit(1);
    // launch 3: gather+split token_feats
    conv_split_gather<<<(MW * 128 + 255) / 256, 256>>>((const float4*)tf, Ahi, Alo);
    // launches 4-5: word input-gate GEMMs
    {
        dim3 g(6, 256);
        gemm_tc<<<g, 256, GEMM_SMEM>>>(Ahi, Alo, Whi, Wlo, w_bih_f, xpw, G3);
        gemm_tc<<<g, 256, GEMM_SMEM>>>(Ahi, Alo, Whi + WSLOT, Wlo + WSLOT, w_bih_b,
                                       xpw + (size_t)MW * G3, G3);
    }
    // launch 6 (ncu-profiled): word BiGRU recurrence
    {
        dim3 g(8, NSEQW / 32, 2);
        gru_reg<LW, 32><<<g, 256>>>(xpw, w_whh_f, w_whh_b, w_bhh_f, w_bhh_b,
                                    hw, outw, bwc, bws, NSEQW);
    }

    // word attention
    conv_split<<<(MW * 128 + 255) / 256, 256>>>((const float4*)outw, Ahi, Alo, MW * 128);
    wsplit(2);
    {
        dim3 g(4, 256);
        gemm_tc<<<g, 256, GEMM_SMEM>>>(Ahi, Alo, Whi + 2 * WSLOT, Wlo + 2 * WSLOT,
                                       w_attn_b, uw, HID);
        attn_reduce<<<NSEQW, 256>>>(uw, outw, w_ctx, sent, LW);
    }

    // sentence input-gate GEMMs
    wsplit(3); wsplit(4);
    conv_split<<<(NSEQW * 128 + 255) / 256, 256>>>((const float4*)sent, Ahi, Alo, NSEQW * 128);
    {
        dim3 g(6, 2);
        gemm_tc<<<g, 256, GEMM_SMEM>>>(Ahi, Alo, Whi + 3 * WSLOT, Wlo + 3 * WSLOT,
                                       s_bih_f, xps, G3);
        gemm_tc<<<g, 256, GEMM_SMEM>>>(Ahi, Alo, Whi + 4 * WSLOT, Wlo + 4 * WSLOT,
                                       s_bih_b, xps + (size_t)BATCH * NSENT * G3, G3);
    }

    // sentence BiGRU
    {
        dim3 g(8, 1, 2);
        gru_reg<NSENT, 16><<<g, 256>>>(xps, s_whh_f, s_whh_b, s_bhh_f, s_bhh_b,
                                       hs, outs, bsc, bss, BATCH);
    }

    // sentence attention -> output
    wsplit(5);
    conv_split<<<(NSEQW * 128 + 255) / 256, 256>>>((const float4*)outs, Ahi, Alo, NSEQW * 128);
    {
        dim3 g(4, 2);
        gemm_tc<<<g, 256, GEMM_SMEM>>>(Ahi, Alo, Whi + 5 * WSLOT, Wlo + 5 * WSLOT,
                                       s_attn_b, us, HID);
        attn_reduce<<<BATCH, 256>>>(us, outs, s_ctx, (float*)d_out, NSENT);
    }
}

// round 8
// speedup vs baseline: 1.2752x; 1.0338x over previous
#include <cuda_runtime.h>
#include <cuda_bf16.h>
#include <math.h>
#include <stdint.h>

// ---------------- problem constants ----------------
#define HID     512      // H
#define HH      256      // Hh
#define G3      768      // 3*Hh
#define BATCH   16
#define NSENT   16
#define LW      128      // word seq len
#define NSEQW   256      // B*Nsent
#define MW      32768    // NSEQW*LW
#define WSLOT   (768 * 512)

// ---------------- device scratch (no mallocs allowed) ----------------
__device__ float g_xpw[2UL * MW * G3];        // word input gates, per dir
__device__ float g_outw[(size_t)MW * HID];    // word BiGRU outputs
__device__ float g_uw[(size_t)MW * HID];      // word attn pre-tanh proj
__device__ float g_sent[NSEQW * HID];         // sentence vectors
__device__ float g_xps[2 * BATCH * NSENT * G3];
__device__ float g_outs[BATCH * NSENT * HID];
__device__ float g_us[BATCH * NSENT * HID];
// h ping-pong, layout [phase][dir][seq][j(256)]
__device__ float g_hw[2 * 2 * HH * NSEQW];
__device__ float g_hs[2 * 2 * HH * BATCH];
__device__ unsigned g_barw_cnt[16], g_barw_sense[16];   // 16 groups of 8 blocks
__device__ unsigned g_bars_cnt[2],  g_bars_sense[2];
// bf16 split planes
__device__ __nv_bfloat16 g_Ahi[(size_t)MW * HID];
__device__ __nv_bfloat16 g_Alo[(size_t)MW * HID];
__device__ __nv_bfloat16 g_Whi[6 * WSLOT];
__device__ __nv_bfloat16 g_Wlo[6 * WSLOT];

// ---------------- helpers ----------------
__device__ __forceinline__ uint32_t smem_u32(const void* p) {
    uint32_t a;
    asm("{ .reg .u64 t; cvta.to.shared.u64 t, %1; cvt.u32.u64 %0, t; }" : "=r"(a) : "l"(p));
    return a;
}
__device__ __forceinline__ void ldsm4(uint32_t* r, uint32_t addr) {
    asm volatile("ldmatrix.sync.aligned.m8n8.x4.shared.b16 {%0,%1,%2,%3}, [%4];"
                 : "=r"(r[0]), "=r"(r[1]), "=r"(r[2]), "=r"(r[3]) : "r"(addr));
}
__device__ __forceinline__ void mma_bf16(float* c, const uint32_t* a, const uint32_t* b) {
    asm volatile("mma.sync.aligned.m16n8k16.row.col.f32.bf16.bf16.f32 "
                 "{%0,%1,%2,%3}, {%4,%5,%6,%7}, {%8,%9}, {%0,%1,%2,%3};"
                 : "+f"(c[0]), "+f"(c[1]), "+f"(c[2]), "+f"(c[3])
                 : "r"(a[0]), "r"(a[1]), "r"(a[2]), "r"(a[3]), "r"(b[0]), "r"(b[1]));
}

// ---------------- fp32 -> (bf16 hi, bf16 lo) split conversions ----------------
__device__ __forceinline__ void split4(float4 v, __nv_bfloat162* h, __nv_bfloat162* l) {
    float x[4] = {v.x, v.y, v.z, v.w};
    __nv_bfloat16 hh[4], ll[4];
#pragma unroll
    for (int i = 0; i < 4; i++) {
        hh[i] = __float2bfloat16_rn(x[i]);
        ll[i] = __float2bfloat16_rn(x[i] - __bfloat162float(hh[i]));
    }
    h[0] = __nv_bfloat162(hh[0], hh[1]); h[1] = __nv_bfloat162(hh[2], hh[3]);
    l[0] = __nv_bfloat162(ll[0], ll[1]); l[1] = __nv_bfloat162(ll[2], ll[3]);
}

__global__ void conv_split(const float4* __restrict__ src,
                           __nv_bfloat16* __restrict__ hi,
                           __nv_bfloat16* __restrict__ lo, int n4) {
    int i = blockIdx.x * blockDim.x + threadIdx.x;
    if (i >= n4) return;
    __nv_bfloat162 h[2], l[2];
    split4(src[i], h, l);
    ((__nv_bfloat162*)hi)[2 * i] = h[0]; ((__nv_bfloat162*)hi)[2 * i + 1] = h[1];
    ((__nv_bfloat162*)lo)[2 * i] = l[0]; ((__nv_bfloat162*)lo)[2 * i + 1] = l[1];
}

// gather variant: row m of A = token_feats[((m&2047)*16 + (m>>11))*512]
__global__ void conv_split_gather(const float4* __restrict__ tf,
                                  __nv_bfloat16* __restrict__ hi,
                                  __nv_bfloat16* __restrict__ lo) {
    int i = blockIdx.x * blockDim.x + threadIdx.x;
    if (i >= MW * 128) return;
    int m = i >> 7, kq = i & 127;
    float4 v = tf[((size_t)((m & 2047) * 16 + (m >> 11))) * 128 + kq];
    __nv_bfloat162 h[2], l[2];
    split4(v, h, l);
    ((__nv_bfloat162*)hi)[2 * i] = h[0]; ((__nv_bfloat162*)hi)[2 * i + 1] = h[1];
    ((__nv_bfloat162*)lo)[2 * i] = l[0]; ((__nv_bfloat162*)lo)[2 * i + 1] = l[1];
}

// ---------------- HMMA GEMM (unchanged, passing) ----------------
#define GEMM_SMEM 131072
__global__ void __launch_bounds__(256, 1)
gemm_tc(const __nv_bfloat16* __restrict__ Ahi, const __nv_bfloat16* __restrict__ Alo,
        const __nv_bfloat16* __restrict__ Bhi, const __nv_bfloat16* __restrict__ Blo,
        const float* __restrict__ bias, float* __restrict__ C, int ldc)
{
    extern __shared__ __align__(128) char smg[];
    const uint32_t sb = smem_u32(smg);
    const int tid = threadIdx.x;
    const int lane = tid & 31, wid = tid >> 5;
    const int wm = wid >> 2, wn = wid & 3;
    const int m0 = blockIdx.y * 128, n0 = blockIdx.x * 128;

    const __nv_bfloat16* planes[4] = {
        Ahi + (size_t)m0 * 512, Alo + (size_t)m0 * 512,
        Bhi + (size_t)n0 * 512, Blo + (size_t)n0 * 512 };

    const int rb = lane & 7;
    const int glA = lane >> 4;
    const int glB = lane >> 3;
    int aoff[4], boff[4];
#pragma unroll
    for (int mt = 0; mt < 4; mt++) {
        int r = wm * 64 + mt * 16 + rb + ((lane >> 3) & 1) * 8;
        aoff[mt] = ((r >> 3) << 10) + (rb << 7);
    }
#pragma unroll
    for (int nt = 0; nt < 4; nt++) {
        int r = wn * 32 + nt * 8 + rb;
        boff[nt] = ((r >> 3) << 10) + (rb << 7);
    }

    float acc[4][4][4];
#pragma unroll
    for (int a = 0; a < 4; a++)
#pragma unroll
        for (int b = 0; b < 4; b++)
#pragma unroll
            for (int d = 0; d < 4; d++) acc[a][b][d] = 0.f;

    const int ldg = tid & 7;
    const int ldr = tid >> 3;

#pragma unroll
    for (int i = 0; i < 16; i++) {
        const int pl = i >> 2;
        const int r = ((i & 3) << 5) + ldr;
        const __nv_bfloat16* src = planes[pl] + (size_t)r * 512 + ldg * 8;
        uint32_t dst = sb + pl * 16384 + ((r >> 3) << 10) + ((r & 7) << 7)
                       + ((ldg ^ (r & 7)) << 4);
        asm volatile("cp.async.cg.shared.global [%0], [%1], 16;" :: "r"(dst), "l"(src));
    }
    asm volatile("cp.async.commit_group;" ::: "memory");

    for (int c = 0; c < 8; c++) {
        asm volatile("cp.async.wait_group 0;" ::: "memory");
        __syncthreads();
        if (c < 7) {
            const int k0 = (c + 1) << 6;
            const uint32_t dbase = sb + ((c + 1) & 1) * 65536;
#pragma unroll
            for (int i = 0; i < 16; i++) {
                const int pl = i >> 2;
                const int r = ((i & 3) << 5) + ldr;
                const __nv_bfloat16* src = planes[pl] + (size_t)r * 512 + k0 + ldg * 8;
                uint32_t dst = dbase + pl * 16384 + ((r >> 3) << 10) + ((r & 7) << 7)
                               + ((ldg ^ (r & 7)) << 4);
                asm volatile("cp.async.cg.shared.global [%0], [%1], 16;" :: "r"(dst), "l"(src));
            }
            asm volatile("cp.async.commit_group;" ::: "memory");
        }

        const uint32_t bbase = sb + (c & 1) * 65536;
        uint32_t Bf[2][4][4];
#pragma unroll
        for (int s = 0; s < 4; s++) {
            if ((s & 1) == 0) {
                const int q0 = s << 1;
#pragma unroll
                for (int pl = 0; pl < 2; pl++)
#pragma unroll
                    for (int nt = 0; nt < 4; nt++)
                        ldsm4(Bf[pl][nt],
                              bbase + (2 + pl) * 16384 + boff[nt]
                              + (((q0 + glB) ^ rb) << 4));
            }
            uint32_t Af[2][4][4];
#pragma unroll
            for (int pl = 0; pl < 2; pl++)
#pragma unroll
                for (int mt = 0; mt < 4; mt++)
                    ldsm4(Af[pl][mt],
                          bbase + pl * 16384 + aoff[mt]
                          + ((((s << 1) + glA) ^ rb) << 4));
            const int ro = (s & 1) << 1;
#pragma unroll
            for (int mt = 0; mt < 4; mt++)
#pragma unroll
                for (int nt = 0; nt < 4; nt++) {
                    mma_bf16(acc[mt][nt], Af[0][mt], &Bf[0][nt][ro]);
                    mma_bf16(acc[mt][nt], Af[0][mt], &Bf[1][nt][ro]);
                    mma_bf16(acc[mt][nt], Af[1][mt], &Bf[0][nt][ro]);
                }
        }
    }

    const int rr = lane >> 2, cc = (lane & 3) * 2;
#pragma unroll
    for (int mt = 0; mt < 4; mt++) {
        const int row = m0 + wm * 64 + mt * 16 + rr;
#pragma unroll
        for (int nt = 0; nt < 4; nt++) {
            const int col = n0 + wn * 32 + nt * 8 + cc;
            const float b0 = bias[col], b1 = bias[col + 1];
            float2 v0 = {acc[mt][nt][0] + b0, acc[mt][nt][1] + b1};
            float2 v1 = {acc[mt][nt][2] + b0, acc[mt][nt][3] + b1};
            *(float2*)(C + (size_t)row * ldc + col) = v0;
            *(float2*)(C + (size_t)(row + 8) * ldc + col) = v1;
        }
    }
}

// ---------------- group barrier (R4/R7-proven) ----------------
__device__ __forceinline__ unsigned ld_acq(const unsigned* p) {
    unsigned v;
    asm volatile("ld.acquire.gpu.u32 %0, [%1];" : "=r"(v) : "l"(p) : "memory");
    return v;
}
__device__ __forceinline__ void group_barrier(unsigned* cnt, unsigned* sense,
                                              unsigned target, int total) {
    __syncthreads();
    if (threadIdx.x == 0) {
        __threadfence();
        unsigned t = atomicAdd(cnt, 1u);
        if (t == (unsigned)(total - 1)) {
            *cnt = 0u;
            asm volatile("red.release.gpu.add.u32 [%0], 1;" :: "l"(sense) : "memory");
        } else {
            while (ld_acq(sense) != target) { }
        }
    }
    __syncthreads();
}

// ---------------- persistent GRU, W_hh in regs, 512 thr, butterfly reduce ---
// grid (8 j-groups, nseq/SPB, 2 dirs); 512 thr = 32 jj x 16 k-slices (16 k ea).
// Thread (jj, ks) holds W[3 gates][k in ks*16..+16) as 24 f32x2 regs.
// hsm swizzled: slice ks of seq s at float offset s*320 + ks*20 -> every
// LDS.128 is a 2-per-bank-slot (the 256B floor), staging STS.128 spreads 4/bank.
// Per 8 seqs: FFMA partials then 4-round butterfly (masks 1,2,4,8); lane ks
// ends owning seq q*8 + (ks&7); lanes ks<8 do the gate math + stores.
template<int T, int SPB>
__global__ void __launch_bounds__(512, 1)
gru_reg(const float* __restrict__ xp_base,
        const float* __restrict__ whh_f, const float* __restrict__ whh_b,
        const float* __restrict__ bhh_f, const float* __restrict__ bhh_b,
        float* __restrict__ hbuf,            // [2][2][nseq][256]
        float* __restrict__ outbuf,
        unsigned* cnt_arr, unsigned* sense_arr, int nseq)
{
    constexpr int NQ = SPB / 8;
    constexpr int HROW = 320;
    __shared__ __align__(16) float hsm[SPB * HROW];
    __shared__ float xs[32 * (SPB + 1)];

    const int tid = threadIdx.x;
    const int jj = tid >> 4;                 // 0..31
    const int ks = tid & 15;                 // k-slice lane
    const int j0 = blockIdx.x * 32;
    const int sg0 = blockIdx.y * SPB;
    const int dir = blockIdx.z;
    const int gidx = blockIdx.z * gridDim.y + blockIdx.y;
    unsigned* bcnt = cnt_arr + gidx;
    unsigned* bsense = sense_arr + gidx;
    const float* whh = dir ? whh_b : whh_f;
    const float* bhh = dir ? bhh_b : bhh_f;
    const float* xp  = xp_base + (size_t)dir * nseq * T * G3;
    const int j = j0 + jj;

    // ---- W_hh into registers (once): 3 gates x 16 k = 24 f32x2 ----
    unsigned long long Wp[3][8];
#pragma unroll
    for (int g = 0; g < 3; g++)
#pragma unroll
        for (int p = 0; p < 4; p++) {
            float4 v = *(const float4*)(whh + ((size_t)(g * 256 + j)) * 256
                                        + ks * 16 + p * 4);
            asm("mov.b64 %0, {%1,%2};" : "=l"(Wp[g][2*p])     : "f"(v.x), "f"(v.y));
            asm("mov.b64 %0, {%1,%2};" : "=l"(Wp[g][2*p + 1]) : "f"(v.z), "f"(v.w));
        }

    const float br = bhh[j], bz = bhh[256 + j], bn = bhh[512 + j];
    const uint32_t hbase = smem_u32(hsm);
    const unsigned base = ld_acq(bsense);
    const bool own = (ks < 8);
    const bool b0 = (ks & 1), b1 = ((ks >> 1) & 1), b2 = ((ks >> 2) & 1);

    float xr_[NQ], xz_[NQ], xn_[NQ];
    if (own) {
        const int tt = dir ? (T - 1) : 0;
#pragma unroll
        for (int q = 0; q < NQ; q++) {
            const float* row = xp + ((size_t)(sg0 + q * 8 + ks) * T + tt) * G3;
            xr_[q] = row[j]; xz_[q] = row[256 + j]; xn_[q] = row[512 + j];
        }
    }

    for (int step = 0; step < T; step++) {
        const int tt = dir ? (T - 1 - step) : step;

        // ---- stage h(t): vectorized LDG.128 + swizzled STS.128 ----
        if (step == 0) {
            for (int e = tid; e < SPB * HROW; e += 512) hsm[e] = 0.f;
        } else {
            const float4* hcur4 = (const float4*)(hbuf
                + ((size_t)((step & 1) * 2 + dir)) * nseq * 256 + (size_t)sg0 * 256);
#pragma unroll
            for (int i = 0; i < SPB / 8; i++) {      // SPB*64 float4 / 512 thr
                int e = tid + i * 512;
                int s = e >> 6, c4 = e & 63;
                float4 v = hcur4[e];
                *(float4*)(hsm + s * HROW + (c4 >> 2) * 20 + (c4 & 3) * 4) = v;
            }
        }
        __syncthreads();

#pragma unroll
        for (int q = 0; q < NQ; q++) {
            // ---- partial dots for the 8 seqs of this group ----
            float v3[3][8];
#pragma unroll
            for (int s8 = 0; s8 < 8; s8++) {
                const int s = q * 8 + s8;
                const uint32_t ha = hbase + (uint32_t)(s * HROW) * 4 + ks * 80;
                unsigned long long a0 = 0ULL, a1 = 0ULL, a2 = 0ULL;
#pragma unroll
                for (int p = 0; p < 4; p++) {
                    unsigned long long h0, h1;
                    asm("ld.shared.v2.b64 {%0,%1}, [%2];"
                        : "=l"(h0), "=l"(h1) : "r"(ha + p * 16));
                    asm("fma.rn.f32x2 %0, %1, %2, %0;" : "+l"(a0) : "l"(Wp[0][2*p]),   "l"(h0));
                    asm("fma.rn.f32x2 %0, %1, %2, %0;" : "+l"(a1) : "l"(Wp[1][2*p]),   "l"(h0));
                    asm("fma.rn.f32x2 %0, %1, %2, %0;" : "+l"(a2) : "l"(Wp[2][2*p]),   "l"(h0));
                    asm("fma.rn.f32x2 %0, %1, %2, %0;" : "+l"(a0) : "l"(Wp[0][2*p+1]), "l"(h1));
                    asm("fma.rn.f32x2 %0, %1, %2, %0;" : "+l"(a1) : "l"(Wp[1][2*p+1]), "l"(h1));
                    asm("fma.rn.f32x2 %0, %1, %2, %0;" : "+l"(a2) : "l"(Wp[2][2*p+1]), "l"(h1));
                }
                float lo, hi;
                asm("mov.b64 {%0,%1}, %2;" : "=f"(lo), "=f"(hi) : "l"(a0)); v3[0][s8] = lo + hi;
                asm("mov.b64 {%0,%1}, %2;" : "=f"(lo), "=f"(hi) : "l"(a1)); v3[1][s8] = lo + hi;
                asm("mov.b64 {%0,%1}, %2;" : "=f"(lo), "=f"(hi) : "l"(a2)); v3[2][s8] = lo + hi;
            }

            // ---- butterfly reduce over 16 k-lanes ----
            float sv[3];
#pragma unroll
            for (int g = 0; g < 3; g++) {
                float t0[4], t1[2];
#pragma unroll
                for (int i = 0; i < 4; i++) {
                    float keep = b0 ? v3[g][2*i + 1] : v3[g][2*i];
                    float send = b0 ? v3[g][2*i]     : v3[g][2*i + 1];
                    t0[i] = keep + __shfl_xor_sync(0xffffffffu, send, 1);
                }
#pragma unroll
                for (int i = 0; i < 2; i++) {
                    float keep = b1 ? t0[2*i + 1] : t0[2*i];
                    float send = b1 ? t0[2*i]     : t0[2*i + 1];
                    t1[i] = keep + __shfl_xor_sync(0xffffffffu, send, 2);
                }
                float keep = b2 ? t1[1] : t1[0];
                float send = b2 ? t1[0] : t1[1];
                float r = keep + __shfl_xor_sync(0xffffffffu, send, 4);
                r += __shfl_xor_sync(0xffffffffu, r, 8);   // join k halves
                sv[g] = r;                                 // seq = q*8 + (ks&7)
            }

            // ---- gates + update (owner lanes ks<8) ----
            if (own) {
                const int s = q * 8 + ks;
                const float hold = hsm[s * HROW + (j >> 4) * 20 + (j & 15)];
                const float r  = 1.f / (1.f + expf(-(xr_[q] + sv[0] + br)));
                const float z  = 1.f / (1.f + expf(-(xz_[q] + sv[1] + bz)));
                const float nn = tanhf(xn_[q] + r * (sv[2] + bn));
                const float hnew = (1.f - z) * nn + z * hold;
                xs[jj * (SPB + 1) + s] = hnew;
                outbuf[((size_t)(sg0 + s) * T + tt) * HID + dir * HH + j] = hnew;
            }
        }
        __syncthreads();

        if (step < T - 1) {
            // coalesced h(t+1) write-out: [seq][j] global layout
            float* hnext = hbuf + ((size_t)(((step + 1) & 1) * 2 + dir)) * nseq * 256
                           + (size_t)sg0 * 256;
#pragma unroll
            for (int e = tid; e < SPB * 32; e += 512) {
                int s = e >> 5, jr = e & 31;
                hnext[s * 256 + j0 + jr] = xs[jr * (SPB + 1) + s];
            }
            // prefetch next step's xp before spinning on the barrier
            const int t2 = dir ? (T - 2 - step) : (step + 1);
            if (own) {
#pragma unroll
                for (int q = 0; q < NQ; q++) {
                    const float* row = xp + ((size_t)(sg0 + q * 8 + ks) * T + t2) * G3;
                    xr_[q] = row[j]; xz_[q] = row[256 + j]; xn_[q] = row[512 + j];
                }
            }
            group_barrier(bcnt, bsense, base + (unsigned)step + 1u, 8);
        }
    }
}

// ---------------- attention reduce (unchanged) ----------------
__global__ __launch_bounds__(256)
void attn_reduce(const float* __restrict__ u,
                 const float* __restrict__ feats,
                 const float* __restrict__ ctx,
                 float* __restrict__ dst,
                 int T)
{
    const int seq = blockIdx.x;
    const int tid = threadIdx.x;
    __shared__ float sctx[512];
    __shared__ float ssc[128];
    __shared__ float sred[256];

    for (int g = tid; g < 512; g += 256) sctx[g] = ctx[g];
    __syncthreads();

    const int lane = tid & 31, warp = tid >> 5;
    for (int t = warp; t < T; t += 8) {
        const float* ur = u + ((size_t)seq * T + t) * 512;
        float p = 0.f;
        for (int g = lane; g < 512; g += 32) p += tanhf(ur[g]) * sctx[g];
#pragma unroll
        for (int o = 16; o; o >>= 1) p += __shfl_down_sync(0xffffffffu, p, o);
        if (lane == 0) ssc[t] = p;
    }
    __syncthreads();

    float v = (tid < T) ? ssc[tid] : -1e30f;
    sred[tid] = v; __syncthreads();
    for (int o = 128; o; o >>= 1) { if (tid < o) sred[tid] = fmaxf(sred[tid], sred[tid + o]); __syncthreads(); }
    float mx = sred[0]; __syncthreads();
    float e = (tid < T) ? expf(v - mx) : 0.f;
    sred[tid] = e; __syncthreads();
    for (int o = 128; o; o >>= 1) { if (tid < o) sred[tid] += sred[tid + o]; __syncthreads(); }
    float inv = 1.f / sred[0]; __syncthreads();
    if (tid < T) ssc[tid] = e * inv;
    __syncthreads();

    for (int h = tid; h < 512; h += 256) {
        float acc = 0.f;
        for (int t = 0; t < T; t++)
            acc = fmaf(ssc[t], feats[((size_t)seq * T + t) * 512 + h], acc);
        dst[(size_t)seq * 512 + h] = acc;
    }
}

// ---------------- host ----------------
extern "C" void kernel_launch(void* const* d_in, const int* in_sizes, int n_in,
                              void* d_out, int out_size)
{
    const float* tf       = (const float*)d_in[0];
    const float* w_wih_f  = (const float*)d_in[2];
    const float* w_whh_f  = (const float*)d_in[3];
    const float* w_bih_f  = (const float*)d_in[4];
    const float* w_bhh_f  = (const float*)d_in[5];
    const float* w_wih_b  = (const float*)d_in[6];
    const float* w_whh_b  = (const float*)d_in[7];
    const float* w_bih_b  = (const float*)d_in[8];
    const float* w_bhh_b  = (const float*)d_in[9];
    const float* s_wih_f  = (const float*)d_in[10];
    const float* s_whh_f  = (const float*)d_in[11];
    const float* s_bih_f  = (const float*)d_in[12];
    const float* s_bhh_f  = (const float*)d_in[13];
    const float* s_wih_b  = (const float*)d_in[14];
    const float* s_whh_b  = (const float*)d_in[15];
    const float* s_bih_b  = (const float*)d_in[16];
    const float* s_bhh_b  = (const float*)d_in[17];
    const float* w_attn_w = (const float*)d_in[18];
    const float* w_attn_b = (const float*)d_in[19];
    const float* w_ctx    = (const float*)d_in[20];
    const float* s_attn_w = (const float*)d_in[21];
    const float* s_attn_b = (const float*)d_in[22];
    const float* s_ctx    = (const float*)d_in[23];

    float *xpw, *outw, *uw, *sent, *xps, *outs, *us, *hw, *hs;
    unsigned *bwc, *bws, *bsc, *bss;
    __nv_bfloat16 *Ahi, *Alo, *Whi, *Wlo;
    cudaGetSymbolAddress((void**)&xpw,  g_xpw);
    cudaGetSymbolAddress((void**)&outw, g_outw);
    cudaGetSymbolAddress((void**)&uw,   g_uw);
    cudaGetSymbolAddress((void**)&sent, g_sent);
    cudaGetSymbolAddress((void**)&xps,  g_xps);
    cudaGetSymbolAddress((void**)&outs, g_outs);
    cudaGetSymbolAddress((void**)&us,   g_us);
    cudaGetSymbolAddress((void**)&hw,   g_hw);
    cudaGetSymbolAddress((void**)&hs,   g_hs);
    cudaGetSymbolAddress((void**)&bwc,  g_barw_cnt);
    cudaGetSymbolAddress((void**)&bws,  g_barw_sense);
    cudaGetSymbolAddress((void**)&bsc,  g_bars_cnt);
    cudaGetSymbolAddress((void**)&bss,  g_bars_sense);
    cudaGetSymbolAddress((void**)&Ahi,  g_Ahi);
    cudaGetSymbolAddress((void**)&Alo,  g_Alo);
    cudaGetSymbolAddress((void**)&Whi,  g_Whi);
    cudaGetSymbolAddress((void**)&Wlo,  g_Wlo);

    cudaFuncSetAttribute(gemm_tc,
                         cudaFuncAttributeMaxDynamicSharedMemorySize, GEMM_SMEM);

    const float* wsrc[6] = {w_wih_f, w_wih_b, w_attn_w, s_wih_f, s_wih_b, s_attn_w};
    const int    wrows[6] = {768, 768, 512, 768, 768, 512};
    auto wsplit = [&](int i) {
        int n4 = wrows[i] * 128;
        conv_split<<<(n4 + 255) / 256, 256>>>((const float4*)wsrc[i],
                                              Whi + (size_t)i * WSLOT,
                                              Wlo + (size_t)i * WSLOT, n4);
    };

    // word weight splits + token gather/split
    wsplit(0); wsplit(1);
    conv_split_gather<<<(MW * 128 + 255) / 256, 256>>>((const float4*)tf, Ahi, Alo);
    // word input-gate GEMMs
    {
        dim3 g(6, 256);
        gemm_tc<<<g, 256, GEMM_SMEM>>>(Ahi, Alo, Whi, Wlo, w_bih_f, xpw, G3);
        gemm_tc<<<g, 256, GEMM_SMEM>>>(Ahi, Alo, Whi + WSLOT, Wlo + WSLOT, w_bih_b,
                                       xpw + (size_t)MW * G3, G3);
    }
    // word BiGRU recurrence (persistent, 16 groups x 8 blocks, 512 thr/block)
    {
        dim3 g(8, NSEQW / 32, 2);
        gru_reg<LW, 32><<<g, 512>>>(xpw, w_whh_f, w_whh_b, w_bhh_f, w_bhh_b,
                                    hw, outw, bwc, bws, NSEQW);
    }

    // word attention
    conv_split<<<(MW * 128 + 255) / 256, 256>>>((const float4*)outw, Ahi, Alo, MW * 128);
    wsplit(2);
    {
        dim3 g(4, 256);
        gemm_tc<<<g, 256, GEMM_SMEM>>>(Ahi, Alo, Whi + 2 * WSLOT, Wlo + 2 * WSLOT,
                                       w_attn_b, uw, HID);
        attn_reduce<<<NSEQW, 256>>>(uw, outw, w_ctx, sent, LW);
    }

    // sentence input-gate GEMMs
    wsplit(3); wsplit(4);
    conv_split<<<(NSEQW * 128 + 255) / 256, 256>>>((const float4*)sent, Ahi, Alo, NSEQW * 128);
    {
        dim3 g(6, 2);
        gemm_tc<<<g, 256, GEMM_SMEM>>>(Ahi, Alo, Whi + 3 * WSLOT, Wlo + 3 * WSLOT,
                                       s_bih_f, xps, G3);
        gemm_tc<<<g, 256, GEMM_SMEM>>>(Ahi, Alo, Whi + 4 * WSLOT, Wlo + 4 * WSLOT,
                                       s_bih_b, xps + (size_t)BATCH * NSENT * G3, G3);
    }

    // sentence BiGRU
    {
        dim3 g(8, 1, 2);
        gru_reg<NSENT, 16><<<g, 512>>>(xps, s_whh_f, s_whh_b, s_bhh_f, s_bhh_b,
                                       hs, outs, bsc, bss, BATCH);
    }

    // sentence attention -> output
    wsplit(5);
    conv_split<<<(NSEQW * 128 + 255) / 256, 256>>>((const float4*)outs, Ahi, Alo, NSEQW * 128);
    {
        dim3 g(4, 2);
        gemm_tc<<<g, 256, GEMM_SMEM>>>(Ahi, Alo, Whi + 5 * WSLOT, Wlo + 5 * WSLOT,
                                       s_attn_b, us, HID);
        attn_reduce<<<BATCH, 256>>>(us, outs, s_ctx, (float*)d_out, NSENT);
    }
}